// round 16
// baseline (speedup 1.0000x reference)
#include <cuda_runtime.h>

// Problem constants (fixed shapes per reference: B=128, C=1, H=W=512, BINS=256)
#define NBINS      256
#define HEIGHT_RT  0.05f
#define NB         128                 // batch
#define NPER       262144              // 512*512 elems per sample
#define BPS        64                  // blocks per sample (16 KB slice each)
#define NBLK       (NB * BPS)          // 8192 blocks
#define OUT_X      ((size_t)NB * NPER) // big output, then NB values

// Scratch (no allocations). Partials fully overwritten each call; counters
// and flags zeroed by reset_kernel before the fused kernel each call.
__device__ unsigned int g_hist_partial[NBLK * NBINS];   // 8 MB
__device__ float        g_w[NB];
__device__ unsigned int g_done[NB];
__device__ volatile unsigned int g_ready[NB];

// ---------------------------------------------------------------------------
// Reset counters/flags (ordered before fused_kernel by the launch boundary).
// ---------------------------------------------------------------------------
__global__ void reset_kernel() {
    g_done[threadIdx.x]  = 0u;
    g_ready[threadIdx.x] = 0u;
}

// ---------------------------------------------------------------------------
// Single-pass kernel. Block = one 4096-elem slice of one sample.
//   1) read slice (fills L2), hist via warp-private smem atomics
//   2) publish 256-bin partial; LAST block of the sample sums 64 partials,
//      computes value + MLP, publishes w (decoupled-lookback handshake)
//   3) re-read slice (L2 hit), scale, streaming-store
// x is read from DRAM ONCE: ~270 MB total vs 402 MB for the 3-kernel layout.
// ---------------------------------------------------------------------------
__global__ __launch_bounds__(256) void fused_kernel(
    const float* __restrict__ x,
    const float* __restrict__ W1, const float* __restrict__ b1,
    const float* __restrict__ W2, const float* __restrict__ b2,
    const float* __restrict__ W3, const float* __restrict__ b3,
    const float* __restrict__ W4, const float* __restrict__ b4,
    float* __restrict__ out, float* __restrict__ out_value)
{
    __shared__ unsigned int sh[8][NBINS];    // 8 KB warp-private hist copies
    __shared__ unsigned int s_old;
    __shared__ float        s_wv;

    const int tid    = threadIdx.x;          // 0..255
    const int lane   = tid & 31;
    const int warp   = tid >> 5;
    const int bid    = blockIdx.x;
    const int sample = bid >> 6;

    #pragma unroll
    for (int c = 0; c < 8; c++) sh[c][tid] = 0u;
    __syncthreads();

    // ---- Phase 1: read slice once (default caching -> L2 fill) + hist ----
    const size_t base = (size_t)bid * 1024 + tid;     // float4 index
    const float4* __restrict__ xin = (const float4*)x + base;
    {
        float4 v0 = xin[0 * 256];
        float4 v1 = xin[1 * 256];
        float4 v2 = xin[2 * 256];
        float4 v3 = xin[3 * 256];
        float vals[16] = {v0.x, v0.y, v0.z, v0.w, v1.x, v1.y, v1.z, v1.w,
                          v2.x, v2.y, v2.z, v2.w, v3.x, v3.y, v3.z, v3.w};
        #pragma unroll
        for (int k = 0; k < 16; k++) {
            float f = vals[k];
            if (f >= 0.0f && f <= 1.0f) {    // torch.histc: out-of-range ignored
                int b = (int)(f * 256.0f);   // floor (f >= 0)
                if (b > 255) b = 255;        // f == 1.0 -> last bin
                atomicAdd(&sh[warp][b], 1u);
            }
        }
    }
    __syncthreads();

    {
        unsigned int s = 0;
        #pragma unroll
        for (int c = 0; c < 8; c++) s += sh[c][tid];
        g_hist_partial[((size_t)bid << 8) + tid] = s;
    }
    __threadfence();                         // publish partial slice
    __syncthreads();
    if (tid == 0) s_old = atomicAdd(&g_done[sample], 1u);
    __syncthreads();

    if (s_old == BPS - 1) {
        // ================= Epilogue (last block of sample) =================
        __threadfence();                     // acquire: siblings' partials
        float*        s_h   = (float*)&sh[0][0];      // reuse smem
        unsigned int* s_red = &sh[4][0];
        unsigned int* s_key = &sh[4][16];
        float*        s_l1p = (float*)&sh[5][0];
        float*        s_h1  = (float*)&sh[6][0];
        float*        s_h2  = (float*)&sh[6][32];
        float*        s_h3  = (float*)&sh[6][96];
        float*        s_p   = (float*)&sh[6][224];
        __syncthreads();                     // done with hist use of sh

        // Sum 64 partials for bin = tid (just-written -> L2 hits; __ldcg
        // bypasses L1 since other SMs wrote them)
        unsigned int cnt = 0;
        {
            const unsigned int* q =
                &g_hist_partial[((size_t)(sample * BPS) << 8) + tid];
            #pragma unroll 8
            for (int b2 = 0; b2 < BPS; b2++) cnt += __ldcg(q + (b2 << 8));
        }
        s_h[tid] = (float)cnt;

        // First-occurrence argmax via packed key (count<<8)|(255-bin):
        // counts <= 262144 < 2^19 -> fits 27 bits; ties -> LOWEST index.
        unsigned int key = (cnt << 8) | (unsigned)(255 - tid);
        #pragma unroll
        for (int o = 16; o > 0; o >>= 1) {
            unsigned int other = __shfl_down_sync(0xffffffffu, key, o);
            if (other > key) key = other;
        }
        if (lane == 0) s_red[warp] = key;
        __syncthreads();
        if (tid == 0) {
            unsigned int k = s_red[0];
            #pragma unroll
            for (int i = 1; i < 8; i++) if (s_red[i] > k) k = s_red[i];
            *s_key = k;
        }
        __syncthreads();

        const int   am = 255 - (int)(*s_key & 255u);
        const float ch = (float)(*s_key >> 8) * HEIGHT_RT;
        __syncthreads();                     // protect s_red reuse

        int mini = (tid >= am && !(s_h[tid] > ch)) ? tid : 0x7fffffff;
        #pragma unroll
        for (int o = 16; o > 0; o >>= 1) {
            int other = __shfl_down_sync(0xffffffffu, mini, o);
            if (other < mini) mini = other;
        }
        if (lane == 0) s_red[warp] = (unsigned)mini;
        __syncthreads();
        if (tid == 0) {
            int m = (int)s_red[0];
            #pragma unroll
            for (int i = 1; i < 8; i++) if ((int)s_red[i] < m) m = (int)s_red[i];
            if (m == 0x7fffffff) m = 0;
            out_value[sample] = (float)m / (float)NBINS;
        }

        // Layer 1: 256 -> 32  (8 partials x 32 outputs)
        {
            const int o = tid & 31, pp = tid >> 5;
            float acc = (pp == 0) ? b1[o] : 0.0f;
            const float* w = W1 + o * 256 + pp * 32;
            const float* h = s_h + pp * 32;
            #pragma unroll
            for (int k = 0; k < 32; k++) acc = fmaf(h[k], w[k], acc);
            s_l1p[pp * 32 + o] = acc;
        }
        __syncthreads();
        if (tid < 32) {
            float a = 0.0f;
            #pragma unroll
            for (int pp = 0; pp < 8; pp++) a += s_l1p[pp * 32 + tid];
            s_h1[tid] = fmaxf(a, 0.0f);
        }
        __syncthreads();

        if (tid < 64) {                      // Layer 2: 32 -> 64
            float acc = b2[tid];
            const float* w = W2 + tid * 32;
            #pragma unroll
            for (int k = 0; k < 32; k++) acc = fmaf(s_h1[k], w[k], acc);
            s_h2[tid] = fmaxf(acc, 0.0f);
        }
        __syncthreads();

        if (tid < 128) {                     // Layer 3: 64 -> 128
            float acc = b3[tid];
            const float* w = W3 + tid * 64;
            #pragma unroll
            for (int k = 0; k < 64; k++) acc = fmaf(s_h2[k], w[k], acc);
            s_h3[tid] = fmaxf(acc, 0.0f);
        }
        __syncthreads();

        float part = (tid < 128) ? s_h3[tid] * W4[tid] : 0.0f;  // Layer 4
        #pragma unroll
        for (int o = 16; o > 0; o >>= 1)
            part += __shfl_down_sync(0xffffffffu, part, o);
        if (lane == 0 && warp < 4) s_p[warp] = part;
        __syncthreads();
        if (tid == 0) {
            float wv = s_p[0] + s_p[1] + s_p[2] + s_p[3] + b4[0];
            s_wv = wv;
            g_w[sample] = wv;
            __threadfence();                 // publish w before flag
            g_ready[sample] = 1u;            // release
        }
        __syncthreads();
    } else {
        // ---------------- Siblings: brief spin for w ----------------------
        if (tid == 0) {
            while (g_ready[sample] == 0u) __nanosleep(64);
            __threadfence();                 // acquire
            s_wv = __ldcg(&g_w[sample]);
        }
        __syncthreads();
    }

    // ---- Phase 3: re-read slice (L2-resident) + scale + streaming store ---
    const float w = s_wv;
    {
        float4 u0 = __ldcs(xin + 0 * 256);   // L2 hit; evict-first on last use
        float4 u1 = __ldcs(xin + 1 * 256);
        float4 u2 = __ldcs(xin + 2 * 256);
        float4 u3 = __ldcs(xin + 3 * 256);
        u0.x *= w; u0.y *= w; u0.z *= w; u0.w *= w;
        u1.x *= w; u1.y *= w; u1.z *= w; u1.w *= w;
        u2.x *= w; u2.y *= w; u2.z *= w; u2.w *= w;
        u3.x *= w; u3.y *= w; u3.z *= w; u3.w *= w;
        float4* __restrict__ o = (float4*)out + base;
        __stcs(o + 0 * 256, u0);
        __stcs(o + 1 * 256, u1);
        __stcs(o + 2 * 256, u2);
        __stcs(o + 3 * 256, u3);
    }
}

// ---------------------------------------------------------------------------
extern "C" void kernel_launch(void* const* d_in, const int* in_sizes, int n_in,
                              void* d_out, int out_size)
{
    const float* x  = (const float*)d_in[0];
    const float* W1 = (const float*)d_in[1];
    const float* b1 = (const float*)d_in[2];
    const float* W2 = (const float*)d_in[3];
    const float* b2 = (const float*)d_in[4];
    const float* W3 = (const float*)d_in[5];
    const float* b3 = (const float*)d_in[6];
    const float* W4 = (const float*)d_in[7];
    const float* b4 = (const float*)d_in[8];

    float* out       = (float*)d_out;
    float* out_value = out + OUT_X;

    reset_kernel<<<1, NB>>>();
    fused_kernel<<<NBLK, 256>>>(x, W1, b1, W2, b2, W3, b3, W4, b4,
                                out, out_value);
    (void)in_sizes; (void)n_in; (void)out_size;
}

// round 17
// speedup vs baseline: 3.6223x; 3.6223x over previous
#include <cuda_runtime.h>

// Problem constants (fixed shapes per reference: B=128, C=1, H=W=512, BINS=256)
#define NBINS      256
#define HEIGHT_RT  0.05f
#define NB         128                 // batch
#define NPER       262144              // 512*512 elems per sample
#define CHUNKS     8                   // hist blocks per sample
#define CHUNK_EL   (NPER / CHUNKS)     // 32768 elems per hist block
#define OUT_X      ((size_t)NB * NPER) // big output, then NB values
#define TILES      8192                // scale tiles of 1024 float4

// Scratch (no allocations). Every slot fully overwritten each call.
__device__ unsigned int g_hist_partial[NB * CHUNKS * NBINS];   // 1 MB
__device__ float        g_w[NB];

// ---------------------------------------------------------------------------
// Kernel 1: per-(sample,chunk) histogram. grid = (CHUNKS, NB), 256 threads.
// Warp-private smem copies + atomics. Measured: 25.8 us, DRAM 68%,
// 5.4 TB/s effective (partial L2 hits from previous replay's scale pass).
// ---------------------------------------------------------------------------
__global__ __launch_bounds__(256) void hist_kernel(const float* __restrict__ x) {
    __shared__ unsigned int sh[8][NBINS];
    const int tid    = threadIdx.x;          // 0..255
    const int warp   = tid >> 5;
    const int sample = blockIdx.y;
    const int chunk  = blockIdx.x;

    #pragma unroll
    for (int c = 0; c < 8; c++) sh[c][tid] = 0u;
    __syncthreads();

    const float4* __restrict__ p =
        (const float4*)(x + (size_t)sample * NPER + (size_t)chunk * CHUNK_EL);
    // 8192 float4 per block; 32 per thread
    #pragma unroll 8
    for (int j = 0; j < 32; j++) {
        float4 v = p[j * 256 + tid];
        float vals[4] = {v.x, v.y, v.z, v.w};
        #pragma unroll
        for (int k = 0; k < 4; k++) {
            float f = vals[k];
            if (f >= 0.0f && f <= 1.0f) {        // torch.histc: out-of-range ignored
                int b = (int)(f * 256.0f);       // floor (f >= 0)
                if (b > 255) b = 255;            // f == 1.0 -> last bin
                atomicAdd(&sh[warp][b], 1u);
            }
        }
    }
    __syncthreads();

    unsigned int s = 0;
    #pragma unroll
    for (int c = 0; c < 8; c++) s += sh[c][tid];
    g_hist_partial[((size_t)sample * CHUNKS + chunk) * NBINS + tid] = s;
}

// ---------------------------------------------------------------------------
// Kernel 2: per-sample threshold value + MLP. grid = NB, 256 threads.
// Fully parallel (no serial scans). Measured: ~3 us.
// ---------------------------------------------------------------------------
__global__ __launch_bounds__(256) void mlp_kernel(
    const float* __restrict__ W1, const float* __restrict__ b1,
    const float* __restrict__ W2, const float* __restrict__ b2,
    const float* __restrict__ W3, const float* __restrict__ b3,
    const float* __restrict__ W4, const float* __restrict__ b4,
    float* __restrict__ out_value)
{
    __shared__ float        s_h[NBINS];
    __shared__ unsigned int s_red[8];
    __shared__ float        s_l1p[8][32];
    __shared__ float        s_h1[32];
    __shared__ float        s_h2[64];
    __shared__ float        s_h3[128];
    __shared__ float        s_p[4];
    __shared__ unsigned int s_key;

    const int b    = blockIdx.x;
    const int tid  = threadIdx.x;   // 0..255
    const int lane = tid & 31;
    const int warp = tid >> 5;      // 0..7

    // Sum 8 chunk partials -> histogram (bin = tid)
    unsigned int cnt;
    {
        unsigned int s = 0;
        const unsigned int* p = &g_hist_partial[(size_t)b * CHUNKS * NBINS + tid];
        #pragma unroll
        for (int c = 0; c < CHUNKS; c++) s += p[c * NBINS];
        cnt = s;
        s_h[tid] = (float)s;
    }

    // First-occurrence argmax via packed key (count<<8)|(255-bin):
    // counts <= 262144 < 2^19 -> fits 27 bits; ties go to LOWEST index.
    unsigned int key = (cnt << 8) | (unsigned)(255 - tid);
    #pragma unroll
    for (int o = 16; o > 0; o >>= 1) {
        unsigned int other = __shfl_down_sync(0xffffffffu, key, o);
        if (other > key) key = other;
    }
    if (lane == 0) s_red[warp] = key;
    __syncthreads();
    if (tid == 0) {
        unsigned int k = s_red[0];
        #pragma unroll
        for (int i = 1; i < 8; i++) if (s_red[i] > k) k = s_red[i];
        s_key = k;
    }
    __syncthreads();

    const int   am = 255 - (int)(s_key & 255u);
    const float ch = (float)(s_key >> 8) * HEIGHT_RT;
    __syncthreads();   // protect s_red reuse

    // First i >= am with h[i] <= ch; default 0 if none.
    int mini = (tid >= am && !(s_h[tid] > ch)) ? tid : 0x7fffffff;
    #pragma unroll
    for (int o = 16; o > 0; o >>= 1) {
        int other = __shfl_down_sync(0xffffffffu, mini, o);
        if (other < mini) mini = other;
    }
    if (lane == 0) s_red[warp] = (unsigned)mini;
    __syncthreads();
    if (tid == 0) {
        int m = (int)s_red[0];
        #pragma unroll
        for (int i = 1; i < 8; i++) if ((int)s_red[i] < m) m = (int)s_red[i];
        if (m == 0x7fffffff) m = 0;
        out_value[b] = (float)m / (float)NBINS;
    }

    // Layer 1: 256 -> 32  (8 partials x 32 outputs)
    {
        const int o = tid & 31, pp = tid >> 5;
        float acc = (pp == 0) ? b1[o] : 0.0f;
        const float* w = W1 + o * 256 + pp * 32;
        const float* h = s_h + pp * 32;
        #pragma unroll
        for (int k = 0; k < 32; k++) acc = fmaf(h[k], w[k], acc);
        s_l1p[pp][o] = acc;
    }
    __syncthreads();
    if (tid < 32) {
        float a = 0.0f;
        #pragma unroll
        for (int pp = 0; pp < 8; pp++) a += s_l1p[pp][tid];
        s_h1[tid] = fmaxf(a, 0.0f);
    }
    __syncthreads();

    // Layer 2: 32 -> 64
    if (tid < 64) {
        float acc = b2[tid];
        const float* w = W2 + tid * 32;
        #pragma unroll
        for (int k = 0; k < 32; k++) acc = fmaf(s_h1[k], w[k], acc);
        s_h2[tid] = fmaxf(acc, 0.0f);
    }
    __syncthreads();

    // Layer 3: 64 -> 128
    if (tid < 128) {
        float acc = b3[tid];
        const float* w = W3 + tid * 64;
        #pragma unroll
        for (int k = 0; k < 64; k++) acc = fmaf(s_h2[k], w[k], acc);
        s_h3[tid] = fmaxf(acc, 0.0f);
    }
    __syncthreads();

    // Layer 4: 128 -> 1 (first 4 warps)
    float part = (tid < 128) ? s_h3[tid] * W4[tid] : 0.0f;
    #pragma unroll
    for (int o = 16; o > 0; o >>= 1)
        part += __shfl_down_sync(0xffffffffu, part, o);
    if (lane == 0 && warp < 4) s_p[warp] = part;
    __syncthreads();
    if (tid == 0)
        g_w[b] = s_p[0] + s_p[1] + s_p[2] + s_p[3] + b4[0];
}

// ---------------------------------------------------------------------------
// Kernel 3: out = x * w[sample], REVERSE tile order. grid = TILES, 256 thr.
// All 4 loads issued BEFORE any store (front-batched LDG, MLP_p1=4) so the
// independent reads overlap the write drain. __ldcs on last-use x;
// __stcs streaming writes. Measured champion configuration.
// ---------------------------------------------------------------------------
__global__ __launch_bounds__(256) void scale_kernel(const float* __restrict__ x,
                                                    float* __restrict__ out)
{
    const int tile   = TILES - 1 - blockIdx.x;    // reverse sweep
    const int sample = tile >> 6;                 // 64 tiles per sample
    const float w    = g_w[sample];

    const size_t base = (size_t)tile * 1024 + threadIdx.x;
    const float4* __restrict__ xin = (const float4*)x   + base;
    float4* __restrict__       o   = (float4*)out       + base;

    float4 v0 = __ldcs(xin + 0 * 256);
    float4 v1 = __ldcs(xin + 1 * 256);
    float4 v2 = __ldcs(xin + 2 * 256);
    float4 v3 = __ldcs(xin + 3 * 256);

    v0.x *= w; v0.y *= w; v0.z *= w; v0.w *= w;
    v1.x *= w; v1.y *= w; v1.z *= w; v1.w *= w;
    v2.x *= w; v2.y *= w; v2.z *= w; v2.w *= w;
    v3.x *= w; v3.y *= w; v3.z *= w; v3.w *= w;

    __stcs(o + 0 * 256, v0);
    __stcs(o + 1 * 256, v1);
    __stcs(o + 2 * 256, v2);
    __stcs(o + 3 * 256, v3);
}

// ---------------------------------------------------------------------------
extern "C" void kernel_launch(void* const* d_in, const int* in_sizes, int n_in,
                              void* d_out, int out_size)
{
    const float* x  = (const float*)d_in[0];
    const float* W1 = (const float*)d_in[1];
    const float* b1 = (const float*)d_in[2];
    const float* W2 = (const float*)d_in[3];
    const float* b2 = (const float*)d_in[4];
    const float* W3 = (const float*)d_in[5];
    const float* b3 = (const float*)d_in[6];
    const float* W4 = (const float*)d_in[7];
    const float* b4 = (const float*)d_in[8];

    float* out       = (float*)d_out;
    float* out_value = out + OUT_X;

    dim3 hgrid(CHUNKS, NB);
    hist_kernel<<<hgrid, 256>>>(x);
    mlp_kernel<<<NB, 256>>>(W1, b1, W2, b2, W3, b3, W4, b4, out_value);
    scale_kernel<<<TILES, 256>>>(x, out);
    (void)in_sizes; (void)n_in; (void)out_size;
}